// round 11
// baseline (speedup 1.0000x reference)
#include <cuda_runtime.h>
#include <cuda_bf16.h>

// ---------------------------------------------------------------------------
// KAN feature extractor, GB300 sm_103a.
//   layer1: KANconv3x3 (1->2) on 28x28 + maxpool2 -> (B,2,14,14)
//   layer2: KANconv3x3 (2->2) on 14x14 + maxpool2 -> (B,2,7,7) -> (B,98)
//
// Spline path: per (interval i, column) precomputed cubic poly coeffs c0..c3
// of p(t) = sum_g w_g B_g(x) (uniform B-spline matrix transform). Row 11 of
// the table is all-zero -> branch-free OOB handling. Output channels packed
// into f32x2 (fma.rn.f32x2).
//
// Parallelism: 2 threads per pooled cell.
//   layer1: split by pool row dy (each thread owns acc[dy][0..1]; kernel-row
//           index compile-time; reduction = shfl max).
//   layer2: split by input channel ci (partial sums; reduction = shfl add).
// ---------------------------------------------------------------------------

#define MAX_B 4096
__device__ float g_mid[MAX_B * 2 * 14 * 14];   // (B,2,14,14)

typedef unsigned long long u64;

__device__ __forceinline__ u64 pack2(float lo, float hi) {
    u64 d;
    asm("mov.b64 %0, {%1, %2};" : "=l"(d) : "f"(lo), "f"(hi));
    return d;
}
__device__ __forceinline__ void unpack2(u64 v, float& lo, float& hi) {
    asm("mov.b64 {%0, %1}, %2;" : "=f"(lo), "=f"(hi) : "l"(v));
}
__device__ __forceinline__ u64 ffma2(u64 a, u64 b, u64 c) {
    u64 d;
    asm("fma.rn.f32x2 %0, %1, %2, %3;" : "=l"(d) : "l"(a), "l"(b), "l"(c));
    return d;
}
__device__ __forceinline__ u64 fadd2(u64 a, u64 b) {
    u64 d;
    asm("add.rn.f32x2 %0, %1, %2;" : "=l"(d) : "l"(a), "l"(b));
    return d;
}

__device__ __forceinline__ float silu_f(float v) {
    return __fdividef(v, 1.0f + __expf(-v));
}

// interval index (11 = zero row if OOB) and local parameter t
__device__ __forceinline__ void interval_t(float x, int& i, float& t) {
    float u  = (x + 2.2f) * 2.5f;
    float fi = floorf(u);
    int   ii = (int)fi;
    t = u - fi;
    i = (ii >= 0 && ii <= 10) ? ii : 11;
}

// poly-coeff float2 entry for (i, cc, m): both o packed. col = o*NC+cc.
template <int NC>
__device__ __forceinline__ float2 coef_entry(const float* __restrict__ sw,
                                             const float* __restrict__ sc,
                                             int i, int cc, int m) {
    float c[2];
#pragma unroll
    for (int o = 0; o < 2; o++) {
        int col = o * NC + cc;
        float s = sc[col];
        float w[4];
#pragma unroll
        for (int g = 0; g < 4; g++) {
            int gg = i - 3 + g;
            w[g] = (gg >= 0 && gg <= 7) ? sw[col * 8 + gg] * s : 0.0f;
        }
        float cm;
        if      (m == 0) cm = (w[0] + 4.0f * w[1] + w[2]) * (1.0f / 6.0f);
        else if (m == 1) cm = (w[2] - w[0]) * 0.5f;
        else if (m == 2) cm = (w[0] - 2.0f * w[1] + w[2]) * 0.5f;
        else             cm = (-w[0] + 3.0f * w[1] - 3.0f * w[2] + w[3]) * (1.0f / 6.0f);
        c[o] = cm;
    }
    return make_float2(c[0], c[1]);
}

// ---------------------------------------------------------------------------
// Layer 1: Cin=1, Cout=2. 2 threads per pooled cell, split by pool row dy.
// Thread computes conv outputs (dy=half, dx=0/1) from input rows
// (2h2-1+half .. +2), kernel rows 0..2 (compile-time).
// ---------------------------------------------------------------------------
#define ROW1 37
__global__ void __launch_bounds__(256)
kan_layer1(const float* __restrict__ x,        // (B,1,28,28)
           const float* __restrict__ base_w,   // (2,1,9)
           const float* __restrict__ spline_w, // (2,1,9,8)
           const float* __restrict__ scaler,   // (2,1,9)
           int B) {
    __shared__ float2 csh[12 * ROW1];
    __shared__ float2 bwsh[9];

    int tid = threadIdx.x;
    for (int idx = tid; idx < 12 * 36; idx += blockDim.x) {
        int i  = idx / 36;
        int r  = idx - i * 36;
        csh[i * ROW1 + r] = coef_entry<9>(spline_w, scaler, i, r >> 2, r & 3);
    }
    for (int idx = tid; idx < 9; idx += blockDim.x)
        bwsh[idx] = make_float2(base_w[idx], base_w[9 + idx]);
    __syncthreads();

    int t     = blockIdx.x * blockDim.x + tid;
    bool live = (t < B * 392);
    int  tc   = live ? t : 0;
    int half  = tc & 1;
    int u     = tc >> 1;
    int b     = u / 196;
    int rem   = u - b * 196;
    int h2    = rem / 14;
    int w2    = rem - h2 * 14;

    const float* xb = x + b * 784;
    int h0 = 2 * h2 - 1 + half;    // first input row for this thread
    int w0 = 2 * w2 - 1;

    float val[3][4];
#pragma unroll
    for (int r = 0; r < 3; r++) {
        int  hh    = h0 + r;
        bool rowok = (hh >= 0) && (hh < 28);
#pragma unroll
        for (int c = 0; c < 4; c++) {
            int  ww = w0 + c;
            bool ok = rowok && (ww >= 0) && (ww < 28);
            val[r][c] = ok ? xb[hh * 28 + ww] : 0.0f;
        }
    }

    u64 acc[2];
    acc[0] = pack2(0.0f, 0.0f);
    acc[1] = pack2(0.0f, 0.0f);
    const u64* bw64 = reinterpret_cast<const u64*>(bwsh);

#pragma unroll
    for (int r = 0; r < 3; r++) {          // kernel row (compile-time)
#pragma unroll
        for (int c = 0; c < 4; c++) {
            float v = val[r][c];
            float s = silu_f(v);
            int   i;
            float tt;
            interval_t(v, i, tt);
            u64 t2 = pack2(tt, tt);
            u64 s2 = pack2(s, s);
            const u64* row = reinterpret_cast<const u64*>(&csh[i * ROW1]);
#pragma unroll
            for (int dx = 0; dx < 2; dx++) {
                int kc = c - dx;
                if (kc < 0 || kc > 2) continue;
                int k = r * 3 + kc;
                u64 c0 = row[k * 4 + 0];
                u64 c1 = row[k * 4 + 1];
                u64 c2 = row[k * 4 + 2];
                u64 c3 = row[k * 4 + 3];
                u64 p  = ffma2(c3, t2, c2);
                p      = ffma2(p,  t2, c1);
                p      = ffma2(p,  t2, c0);
                u64 a  = acc[dx];
                a      = ffma2(bw64[k], s2, a);
                acc[dx] = fadd2(a, p);
            }
        }
    }

    // max over own dx pair, then over the partner's dy
    float a0, a1, b0, b1;
    unpack2(acc[0], a0, b0);
    unpack2(acc[1], a1, b1);
    float m0 = fmaxf(a0, a1);
    float m1 = fmaxf(b0, b1);
    u64 m   = pack2(m0, m1);
    u64 pm  = __shfl_xor_sync(0xFFFFFFFFu, m, 1);
    float p0, p1;
    unpack2(pm, p0, p1);
    m0 = fmaxf(m0, p0);
    m1 = fmaxf(m1, p1);

    if (live) {
        // half 0 writes channel 0, half 1 writes channel 1
        float outv = half ? m1 : m0;
        g_mid[b * 392 + half * 196 + h2 * 14 + w2] = outv;
    }
}

// ---------------------------------------------------------------------------
// Layer 2: Cin=2, Cout=2 on 14x14. 2 threads per pooled cell, split by ci.
// Partial acc[dy][dx] summed across the lane pair via shfl, then max.
// ---------------------------------------------------------------------------
#define ROW2 73
__global__ void __launch_bounds__(256)
kan_layer2(const float* __restrict__ base_w,   // (2,2,9)
           const float* __restrict__ spline_w, // (2,2,9,8)
           const float* __restrict__ scaler,   // (2,2,9)
           float* __restrict__ out,            // (B,98)
           int B) {
    __shared__ float2 csh[12 * ROW2];
    __shared__ float2 bwsh[18];

    int tid = threadIdx.x;
    for (int idx = tid; idx < 12 * 72; idx += blockDim.x) {
        int i  = idx / 72;
        int r  = idx - i * 72;
        csh[i * ROW2 + r] = coef_entry<18>(spline_w, scaler, i, r >> 2, r & 3);
    }
    for (int idx = tid; idx < 18; idx += blockDim.x)
        bwsh[idx] = make_float2(base_w[idx], base_w[18 + idx]);
    __syncthreads();

    int t     = blockIdx.x * blockDim.x + tid;
    bool live = (t < B * 98);
    int  tc   = live ? t : 0;
    int ci    = tc & 1;
    int u     = tc >> 1;
    int b     = u / 49;
    int rem   = u - b * 49;
    int h2    = rem / 7;
    int w2    = rem - h2 * 7;

    int h0 = 2 * h2 - 1;
    int w0 = 2 * w2 - 1;

    const float* mb = g_mid + b * 392 + ci * 196;
    float val[4][4];
#pragma unroll
    for (int r = 0; r < 4; r++) {
        int  hh    = h0 + r;
        bool rowok = (hh >= 0) && (hh < 14);
#pragma unroll
        for (int c = 0; c < 4; c++) {
            int  ww = w0 + c;
            bool ok = rowok && (ww >= 0) && (ww < 14);
            val[r][c] = ok ? mb[hh * 14 + ww] : 0.0f;
        }
    }

    u64 acc[2][2];
#pragma unroll
    for (int dy = 0; dy < 2; dy++)
#pragma unroll
        for (int dx = 0; dx < 2; dx++) acc[dy][dx] = pack2(0.0f, 0.0f);

    const u64* bw64 = reinterpret_cast<const u64*>(bwsh) + ci * 9;

#pragma unroll
    for (int r = 0; r < 4; r++) {
#pragma unroll
        for (int c = 0; c < 4; c++) {
            float v = val[r][c];
            float s = silu_f(v);
            int   i;
            float tt;
            interval_t(v, i, tt);
            u64 t2 = pack2(tt, tt);
            u64 s2 = pack2(s, s);
            const u64* row = reinterpret_cast<const u64*>(&csh[i * ROW2]) + ci * 36;
#pragma unroll
            for (int dy = 0; dy < 2; dy++) {
                if (r - dy < 0 || r - dy > 2) continue;
#pragma unroll
                for (int dx = 0; dx < 2; dx++) {
                    if (c - dx < 0 || c - dx > 2) continue;
                    int k = (r - dy) * 3 + (c - dx);
                    u64 c0 = row[k * 4 + 0];
                    u64 c1 = row[k * 4 + 1];
                    u64 c2 = row[k * 4 + 2];
                    u64 c3 = row[k * 4 + 3];
                    u64 p  = ffma2(c3, t2, c2);
                    p      = ffma2(p,  t2, c1);
                    p      = ffma2(p,  t2, c0);
                    u64 a  = acc[dy][dx];
                    a      = ffma2(bw64[k], s2, a);
                    acc[dy][dx] = fadd2(a, p);
                }
            }
        }
    }

    // sum ci partials across lane pair, then max over (dy,dx)
#pragma unroll
    for (int dy = 0; dy < 2; dy++)
#pragma unroll
        for (int dx = 0; dx < 2; dx++)
            acc[dy][dx] = fadd2(acc[dy][dx],
                                __shfl_xor_sync(0xFFFFFFFFu, acc[dy][dx], 1));

    float a00, a01, a10, a11, b00, b01, b10, b11;
    unpack2(acc[0][0], a00, b00);
    unpack2(acc[0][1], a01, b01);
    unpack2(acc[1][0], a10, b10);
    unpack2(acc[1][1], a11, b11);
    float m0 = fmaxf(fmaxf(a00, a01), fmaxf(a10, a11));
    float m1 = fmaxf(fmaxf(b00, b01), fmaxf(b10, b11));

    if (live) {
        // lane ci=0 writes channel 0, ci=1 writes channel 1
        float outv = ci ? m1 : m0;
        out[b * 98 + ci * 49 + h2 * 7 + w2] = outv;
    }
}

extern "C" void kernel_launch(void* const* d_in, const int* in_sizes, int n_in,
                              void* d_out, int out_size) {
    const float *x = 0, *bw1 = 0, *sw1 = 0, *sc1 = 0, *bw2 = 0, *sw2 = 0, *sc2 = 0;
    if (n_in == 7) {
        for (int i = 0; i < n_in; i++) {
            int s = in_sizes[i];
            const float* p = (const float*)d_in[i];
            if      (s == 144) sw1 = p;
            else if (s == 288) sw2 = p;
            else if (s == 18)  { if (!bw1) bw1 = p; else sc1 = p; }
            else if (s == 36)  { if (!bw2) bw2 = p; else sc2 = p; }
            else               x = p;
        }
    }
    if (!x || !bw1 || !sw1 || !sc1 || !bw2 || !sw2 || !sc2) {
        x   = (const float*)d_in[0];
        bw1 = (const float*)d_in[1];
        sw1 = (const float*)d_in[2];
        sc1 = (const float*)d_in[3];
        bw2 = (const float*)d_in[4];
        sw2 = (const float*)d_in[5];
        sc2 = (const float*)d_in[6];
    }
    float* out = (float*)d_out;

    int B = out_size / 98;
    if (B > MAX_B) B = MAX_B;

    int n1 = B * 392;   // 2 threads per layer1 cell
    int n2 = B * 98;    // 2 threads per layer2 cell
    kan_layer1<<<(n1 + 255) / 256, 256>>>(x, bw1, sw1, sc1, B);
    kan_layer2<<<(n2 + 255) / 256, 256>>>(bw2, sw2, sc2, out, B);
}